// round 1
// baseline (speedup 1.0000x reference)
#include <cuda_runtime.h>
#include <cuda_bf16.h>

// Problem constants
#define B   32
#define C   128
#define H   64
#define W   64
#define KM  4      // number of mixing kernels
#define O   256
#define RED 32
#define HW  4096   // H*W
#define KDIM 1152  // C*9

// Scratch (device globals — no allocation)
__device__ float g_pooled[B * C];          // [B,C]
__device__ float g_att[B * KM];            // [B,K]
__device__ float g_wk[(size_t)B * O * KDIM]; // [B,O,C,3,3]  ~37.7MB

// ---------------------------------------------------------------------------
// 1) Global average pool: pooled[b,c] = mean(x[b,c,:,:])
// ---------------------------------------------------------------------------
__global__ void pool_kernel(const float* __restrict__ x) {
    int bc = blockIdx.x;                       // 0..B*C-1
    const float* p = x + (size_t)bc * HW;
    float s = 0.f;
    for (int i = threadIdx.x; i < HW; i += 256) s += p[i];
    // warp reduce
    #pragma unroll
    for (int o = 16; o; o >>= 1) s += __shfl_down_sync(0xFFFFFFFFu, s, o);
    __shared__ float sm[8];
    if ((threadIdx.x & 31) == 0) sm[threadIdx.x >> 5] = s;
    __syncthreads();
    if (threadIdx.x < 8) {
        float v = sm[threadIdx.x];
        #pragma unroll
        for (int o = 4; o; o >>= 1) v += __shfl_down_sync(0xFFu, v, o);
        if (threadIdx.x == 0) g_pooled[bc] = v * (1.f / (float)HW);
    }
}

// ---------------------------------------------------------------------------
// 2) Attention: h = relu(pooled @ w1^T + b1); att = softmax(h @ w2^T + b2)
//    One thread per batch sample.
// ---------------------------------------------------------------------------
__global__ void attn_kernel(const float* __restrict__ w1, const float* __restrict__ b1,
                            const float* __restrict__ w2, const float* __restrict__ b2) {
    int b = threadIdx.x;
    if (b >= B) return;
    const float* pb = g_pooled + b * C;
    float h[RED];
    #pragma unroll 4
    for (int r = 0; r < RED; r++) {
        float s = b1[r];
        const float* wr = w1 + r * C;
        #pragma unroll 8
        for (int c = 0; c < C; c++) s += pb[c] * wr[c];
        h[r] = fmaxf(s, 0.f);
    }
    float logits[KM];
    float mx = -1e30f;
    #pragma unroll
    for (int k = 0; k < KM; k++) {
        float s = b2[k];
        const float* wr = w2 + k * RED;
        #pragma unroll
        for (int r = 0; r < RED; r++) s += h[r] * wr[r];
        logits[k] = s;
        mx = fmaxf(mx, s);
    }
    float den = 0.f;
    #pragma unroll
    for (int k = 0; k < KM; k++) { logits[k] = __expf(logits[k] - mx); den += logits[k]; }
    float inv = 1.f / den;
    #pragma unroll
    for (int k = 0; k < KM; k++) g_att[b * KM + k] = logits[k] * inv;
}

// ---------------------------------------------------------------------------
// 3) Mix kernels: wk[b,o,:] = sum_k att[b,k] * weights[k,o,:]   (float4)
// ---------------------------------------------------------------------------
__global__ void mix_kernel(const float* __restrict__ weights) {
    const int per_b4 = O * (KDIM / 4);   // 73728 float4 per batch (== per-k stride too)
    int i = blockIdx.x * 256 + threadIdx.x;
    if (i >= B * per_b4) return;
    int b = i / per_b4;
    int rem = i - b * per_b4;
    float a0 = g_att[b * KM + 0], a1 = g_att[b * KM + 1];
    float a2 = g_att[b * KM + 2], a3 = g_att[b * KM + 3];
    const float4* w4 = (const float4*)weights;
    float4 v0 = w4[0 * per_b4 + rem];
    float4 v1 = w4[1 * per_b4 + rem];
    float4 v2 = w4[2 * per_b4 + rem];
    float4 v3 = w4[3 * per_b4 + rem];
    float4 r;
    r.x = a0 * v0.x + a1 * v1.x + a2 * v2.x + a3 * v3.x;
    r.y = a0 * v0.y + a1 * v1.y + a2 * v2.y + a3 * v3.y;
    r.z = a0 * v0.z + a1 * v1.z + a2 * v2.z + a3 * v3.z;
    r.w = a0 * v0.w + a1 * v1.w + a2 * v2.w + a3 * v3.w;
    ((float4*)g_wk)[i] = r;
}

// ---------------------------------------------------------------------------
// 4) Per-sample conv as implicit GEMM:
//    out[b][m][n] = sum_k wk[b][m][k] * im2col_x[b][k][n]
//    M=256 (o), N=4096 (pixels), K=1152 (c*9).  128x128x8 tiles, 8x8 per thread.
// ---------------------------------------------------------------------------
#define BM 128
#define BN 128
#define BK 8

__global__ void __launch_bounds__(256, 2)
conv_kernel(const float* __restrict__ x, float* __restrict__ out) {
    int b  = blockIdx.z;
    int m0 = blockIdx.y * BM;
    int n0 = blockIdx.x * BN;

    const float* A = g_wk + (size_t)b * O * KDIM;    // [256][1152]
    const float* X = x    + (size_t)b * C * HW;      // [128][64][64]
    float*       Ob = out + (size_t)b * O * HW;      // [256][4096]

    __shared__ float As[BK][BM];
    __shared__ float Bs[BK][BN];

    int tid = threadIdx.x;
    int tm = tid >> 4;        // 0..15
    int tn = tid & 15;        // 0..15

    // A tile load mapping: 128 rows x 8 cols; each thread loads one float4
    int arow = tid >> 1;            // 0..127
    int acol = (tid & 1) * 4;       // 0 or 4
    // B tile load mapping: 8 k-rows x 128 n-cols; each thread builds one float4
    int bkr = tid >> 5;             // 0..7
    int bnc = (tid & 31) * 4;       // 0..124

    float acc[8][8];
    #pragma unroll
    for (int i = 0; i < 8; i++)
        #pragma unroll
        for (int j = 0; j < 8; j++) acc[i][j] = 0.f;

    for (int k0 = 0; k0 < KDIM; k0 += BK) {
        // --- load A tile (wk), transpose into As[k][m] ---
        float4 av = *(const float4*)(A + (size_t)(m0 + arow) * KDIM + k0 + acol);
        As[acol + 0][arow] = av.x;
        As[acol + 1][arow] = av.y;
        As[acol + 2][arow] = av.z;
        As[acol + 3][arow] = av.w;

        // --- load B tile via on-the-fly im2col ---
        int kg = k0 + bkr;
        int c  = kg / 9;
        int r  = kg - c * 9;
        int dy = r / 3 - 1;
        int dx = r - (r / 3) * 3 - 1;
        const float* Xc = X + c * HW;
        float4 bv;
        {
            int n = n0 + bnc;
            int y = n >> 6, xx = n & 63;
            int iy = y + dy;
            float v0 = 0.f, v1 = 0.f, v2 = 0.f, v3 = 0.f;
            if ((unsigned)iy < (unsigned)H) {
                const float* row = Xc + iy * W;
                int ix0 = xx + dx;
                if ((unsigned)(ix0 + 0) < (unsigned)W) v0 = row[ix0 + 0];
                if ((unsigned)(ix0 + 1) < (unsigned)W) v1 = row[ix0 + 1];
                if ((unsigned)(ix0 + 2) < (unsigned)W) v2 = row[ix0 + 2];
                if ((unsigned)(ix0 + 3) < (unsigned)W) v3 = row[ix0 + 3];
            }
            bv = make_float4(v0, v1, v2, v3);
        }
        *(float4*)&Bs[bkr][bnc] = bv;

        __syncthreads();

        #pragma unroll
        for (int kk = 0; kk < BK; kk++) {
            float4 a0 = *(const float4*)&As[kk][tm * 8];
            float4 a1 = *(const float4*)&As[kk][tm * 8 + 4];
            float4 b0 = *(const float4*)&Bs[kk][tn * 8];
            float4 b1 = *(const float4*)&Bs[kk][tn * 8 + 4];
            float aa[8] = {a0.x, a0.y, a0.z, a0.w, a1.x, a1.y, a1.z, a1.w};
            float bb[8] = {b0.x, b0.y, b0.z, b0.w, b1.x, b1.y, b1.z, b1.w};
            #pragma unroll
            for (int i = 0; i < 8; i++)
                #pragma unroll
                for (int j = 0; j < 8; j++)
                    acc[i][j] += aa[i] * bb[j];
        }
        __syncthreads();
    }

    // --- write 8x8 micro-tile ---
    #pragma unroll
    for (int i = 0; i < 8; i++) {
        float* op = Ob + (size_t)(m0 + tm * 8 + i) * HW + n0 + tn * 8;
        ((float4*)op)[0] = make_float4(acc[i][0], acc[i][1], acc[i][2], acc[i][3]);
        ((float4*)op)[1] = make_float4(acc[i][4], acc[i][5], acc[i][6], acc[i][7]);
    }
}

// ---------------------------------------------------------------------------
extern "C" void kernel_launch(void* const* d_in, const int* in_sizes, int n_in,
                              void* d_out, int out_size) {
    const float* x       = (const float*)d_in[0];
    const float* weights = (const float*)d_in[1];
    const float* w1      = (const float*)d_in[2];
    const float* b1      = (const float*)d_in[3];
    const float* w2      = (const float*)d_in[4];
    const float* b2      = (const float*)d_in[5];
    float* out = (float*)d_out;

    pool_kernel<<<B * C, 256>>>(x);
    attn_kernel<<<1, 32>>>(w1, b1, w2, b2);
    {
        int total4 = B * O * (KDIM / 4);
        mix_kernel<<<(total4 + 255) / 256, 256>>>(weights);
    }
    {
        dim3 grid(HW / BN, O / BM, B);   // (32, 2, 32)
        conv_kernel<<<grid, 256>>>(x, out);
    }
}